// round 1
// baseline (speedup 1.0000x reference)
#include <cuda_runtime.h>

#define BB 8
#define NN 2048
#define DD 256
#define BN (BB * NN)

// scratch for XW = inp @ W  (allocation-free per harness rules)
__device__ float g_xw[BN * DD];

// ---------------------------------------------------------------------------
// Kernel 1: XW = inp @ W   (no bias here; bias added after attention)
// 64x64 tile, k-chunk 32, 256 threads, 4x4 microtile
// ---------------------------------------------------------------------------
__global__ void __launch_bounds__(256) xw_kernel(const float* __restrict__ inp,
                                                 const float* __restrict__ W) {
    __shared__ float As[32][68];
    __shared__ float Bs[32][68];
    const int tid = threadIdx.x;
    const int tx = tid & 15, ty = tid >> 4;
    const int r0 = blockIdx.x * 64;
    const int c0 = blockIdx.y * 64;

    float acc[4][4] = {};

    for (int kk = 0; kk < DD; kk += 32) {
        const int ka = tid & 31, ia0 = tid >> 5;
#pragma unroll
        for (int s = 0; s < 8; s++) {
            const int i = ia0 + s * 8;
            As[ka][i] = inp[(size_t)(r0 + i) * DD + kk + ka];
        }
        const int jb = tid & 63, kb0 = tid >> 6;
#pragma unroll
        for (int s = 0; s < 8; s++) {
            const int k = kb0 + s * 4;
            Bs[k][jb] = W[(size_t)(kk + k) * DD + c0 + jb];
        }
        __syncthreads();
#pragma unroll 8
        for (int k = 0; k < 32; k++) {
            const float4 a = *(const float4*)&As[k][4 * ty];
            const float4 b = *(const float4*)&Bs[k][4 * tx];
            acc[0][0] += a.x * b.x; acc[0][1] += a.x * b.y; acc[0][2] += a.x * b.z; acc[0][3] += a.x * b.w;
            acc[1][0] += a.y * b.x; acc[1][1] += a.y * b.y; acc[1][2] += a.y * b.z; acc[1][3] += a.y * b.w;
            acc[2][0] += a.z * b.x; acc[2][1] += a.z * b.y; acc[2][2] += a.z * b.z; acc[2][3] += a.z * b.w;
            acc[3][0] += a.w * b.x; acc[3][1] += a.w * b.y; acc[3][2] += a.w * b.z; acc[3][3] += a.w * b.w;
        }
        __syncthreads();
    }

#pragma unroll
    for (int i = 0; i < 4; i++) {
        float4 o = make_float4(acc[i][0], acc[i][1], acc[i][2], acc[i][3]);
        *(float4*)&g_xw[(size_t)(r0 + 4 * ty + i) * DD + c0 + 4 * tx] = o;
    }
}

// ---------------------------------------------------------------------------
// Kernel 2: fused attention.
// One CTA = 64 query rows of one batch. Single pass over m (no max-subtract
// in the reference, so num/denom accumulate without rescaling).
// smem: Qs[256][68] (k-major), Ks[256][68] (k-major), Vs[64][256], Ps[64][68]
// ---------------------------------------------------------------------------
#define TI 64
#define TM 64

// smem float offsets
#define OFF_QS 0
#define OFF_KS (OFF_QS + 256 * 68)
#define OFF_VS (OFF_KS + 256 * 68)
#define OFF_PS (OFF_VS + 64 * 256)
#define OFF_DEN (OFF_PS + 64 * 68)
#define OFF_BS (OFF_DEN + 64)
#define SMEM_FLOATS (OFF_BS + 256)

extern __shared__ float smem[];

__global__ void __launch_bounds__(256) attn_kernel(const float* __restrict__ inp,
                                                   const float* __restrict__ adj,
                                                   const float* __restrict__ bvec,
                                                   float* __restrict__ out) {
    const int tid = threadIdx.x;
    const int tx = tid & 15, ty = tid >> 4;
    const int bb = blockIdx.x >> 5;          // 32 row-tiles per batch
    const int i0 = (blockIdx.x & 31) * TI;

    const float* __restrict__ inpB = inp + (size_t)bb * NN * DD;
    const float* __restrict__ adjB = adj + (size_t)bb * NN * NN;
    const float* __restrict__ xwB = g_xw + (size_t)bb * NN * DD;
    float* __restrict__ outB = out + (size_t)bb * NN * DD;

    float* Qs = smem + OFF_QS;   // [k][i] stride 68
    float* Ks = smem + OFF_KS;   // [k][m] stride 68
    float* Vs = smem + OFF_VS;   // [m][c] stride 256
    float* Ps = smem + OFF_PS;   // [r][m] stride 68
    float* denom = smem + OFF_DEN;
    float* bs = smem + OFF_BS;

    if (tid < 64) denom[tid] = 0.0f;
    bs[tid] = bvec[tid];

    // load Q tile transposed (one-time)
    for (int idx = tid; idx < TI * DD; idx += 256) {
        const int i = idx >> 8;
        const int k = idx & 255;
        Qs[k * 68 + i] = inpB[(size_t)(i0 + i) * DD + k];
    }

    float4 acc[4][4];
#pragma unroll
    for (int i = 0; i < 4; i++)
#pragma unroll
        for (int j = 0; j < 4; j++) acc[i][j] = make_float4(0.f, 0.f, 0.f, 0.f);

    const float scale = 0.0625f;  // 1/sqrt(256)

    for (int m0 = 0; m0 < NN; m0 += TM) {
        __syncthreads();  // prev PV done (and Q loaded, first iter)

        // load K tile transposed + V tile row-major
        for (int idx = tid; idx < TM * DD; idx += 256) {
            const int m = idx >> 8;
            const int k = idx & 255;
            Ks[k * 68 + m] = inpB[(size_t)(m0 + m) * DD + k];
        }
        for (int idx = tid; idx < TM * DD; idx += 256) {
            const int m = idx >> 8;
            const int c = idx & 255;
            Vs[m * 256 + c] = xwB[(size_t)(m0 + m) * DD + c];
        }
        __syncthreads();

        // S = Q K^T  (4x4 microtile)
        float s[4][4] = {};
#pragma unroll 8
        for (int k = 0; k < DD; k++) {
            const float4 q = *(const float4*)&Qs[k * 68 + 4 * ty];
            const float4 kv = *(const float4*)&Ks[k * 68 + 4 * tx];
            s[0][0] += q.x * kv.x; s[0][1] += q.x * kv.y; s[0][2] += q.x * kv.z; s[0][3] += q.x * kv.w;
            s[1][0] += q.y * kv.x; s[1][1] += q.y * kv.y; s[1][2] += q.y * kv.z; s[1][3] += q.y * kv.w;
            s[2][0] += q.z * kv.x; s[2][1] += q.z * kv.y; s[2][2] += q.z * kv.z; s[2][3] += q.z * kv.w;
            s[3][0] += q.w * kv.x; s[3][1] += q.w * kv.y; s[3][2] += q.w * kv.z; s[3][3] += q.w * kv.w;
        }

        // P = exp(S*scale) * adj; accumulate row sums; stage P to smem
#pragma unroll
        for (int i = 0; i < 4; i++) {
            const int r = 4 * ty + i;
            const float4 a4 = *(const float4*)&adjB[(size_t)(i0 + r) * NN + m0 + 4 * tx];
            const float p0 = __expf(s[i][0] * scale) * a4.x;
            const float p1 = __expf(s[i][1] * scale) * a4.y;
            const float p2 = __expf(s[i][2] * scale) * a4.z;
            const float p3 = __expf(s[i][3] * scale) * a4.w;
            atomicAdd(&denom[r], (p0 + p1) + (p2 + p3));
            *(float4*)&Ps[r * 68 + 4 * tx] = make_float4(p0, p1, p2, p3);
        }
        __syncthreads();

        // acc += P @ V   (4 rows x 16 cols per thread, cols 4tx + 64j)
#pragma unroll 4
        for (int m = 0; m < TM; m++) {
            const float4 v0 = *(const float4*)&Vs[m * 256 + 4 * tx];
            const float4 v1 = *(const float4*)&Vs[m * 256 + 4 * tx + 64];
            const float4 v2 = *(const float4*)&Vs[m * 256 + 4 * tx + 128];
            const float4 v3 = *(const float4*)&Vs[m * 256 + 4 * tx + 192];
#pragma unroll
            for (int i = 0; i < 4; i++) {
                const float p = Ps[(4 * ty + i) * 68 + m];
                acc[i][0].x += p * v0.x; acc[i][0].y += p * v0.y; acc[i][0].z += p * v0.z; acc[i][0].w += p * v0.w;
                acc[i][1].x += p * v1.x; acc[i][1].y += p * v1.y; acc[i][1].z += p * v1.z; acc[i][1].w += p * v1.w;
                acc[i][2].x += p * v2.x; acc[i][2].y += p * v2.y; acc[i][2].z += p * v2.z; acc[i][2].w += p * v2.w;
                acc[i][3].x += p * v3.x; acc[i][3].y += p * v3.y; acc[i][3].z += p * v3.z; acc[i][3].w += p * v3.w;
            }
        }
    }
    __syncthreads();  // all denom atomics visible

    // epilogue: out = leaky_relu(acc/denom + b)
#pragma unroll
    for (int i = 0; i < 4; i++) {
        const int r = 4 * ty + i;
        const float invd = 1.0f / (denom[r] + 1e-10f);
#pragma unroll
        for (int j = 0; j < 4; j++) {
            const int c = 4 * tx + 64 * j;
            float4 o;
            o.x = acc[i][j].x * invd + bs[c + 0];
            o.y = acc[i][j].y * invd + bs[c + 1];
            o.z = acc[i][j].z * invd + bs[c + 2];
            o.w = acc[i][j].w * invd + bs[c + 3];
            o.x = o.x > 0.f ? o.x : 0.01f * o.x;
            o.y = o.y > 0.f ? o.y : 0.01f * o.y;
            o.z = o.z > 0.f ? o.z : 0.01f * o.z;
            o.w = o.w > 0.f ? o.w : 0.01f * o.w;
            *(float4*)&outB[(size_t)(i0 + r) * DD + c] = o;
        }
    }
}

// ---------------------------------------------------------------------------
extern "C" void kernel_launch(void* const* d_in, const int* in_sizes, int n_in,
                              void* d_out, int out_size) {
    const float* inp = (const float*)d_in[0];
    const float* adj = (const float*)d_in[1];
    const float* W = (const float*)d_in[2];
    const float* b = (const float*)d_in[3];
    float* out = (float*)d_out;

    xw_kernel<<<dim3(BN / 64, DD / 64), 256>>>(inp, W);

    const size_t smem_bytes = SMEM_FLOATS * sizeof(float);
    cudaFuncSetAttribute(attn_kernel, cudaFuncAttributeMaxDynamicSharedMemorySize,
                         (int)smem_bytes);
    attn_kernel<<<BB * (NN / TI), 256, smem_bytes>>>(inp, adj, b, out);
}

// round 3
// speedup vs baseline: 4.2716x; 4.2716x over previous
#include <cuda_runtime.h>
#include <cuda_bf16.h>
#include <stdint.h>

#define BB 8
#define NN 2048
#define DD 256
#define BN (BB * NN)
#define TM 64
#define NCHUNK (NN / TM)

// ---------------- device scratch (allocation-free) ----------------
__device__ __nv_bfloat16 g_xhi[BN * DD];        // X row-major hi
__device__ __nv_bfloat16 g_xlo[BN * DD];        // X row-major lo
__device__ __nv_bfloat16 g_xthi[BB * DD * NN];  // X^T [b][k][m] hi
__device__ __nv_bfloat16 g_xtlo[BB * DD * NN];  // X^T [b][k][m] lo
__device__ __nv_bfloat16 g_wthi[DD * DD];       // W^T [n][k] hi
__device__ __nv_bfloat16 g_wtlo[DD * DD];       // W^T [n][k] lo
__device__ float g_y[BN * DD];                  // Y = attn @ X (normalized)

// ---------------- helpers ----------------
__device__ __forceinline__ uint32_t smem_u32(const void* p) {
    uint32_t a;
    asm("{ .reg .u64 t; cvta.to.shared.u64 t, %1; cvt.u32.u64 %0, t; }" : "=r"(a) : "l"(p));
    return a;
}
__device__ __forceinline__ void ldsm4(uint32_t* r, uint32_t a) {
    asm volatile("ldmatrix.sync.aligned.m8n8.x4.shared.b16 {%0,%1,%2,%3}, [%4];"
                 : "=r"(r[0]), "=r"(r[1]), "=r"(r[2]), "=r"(r[3]) : "r"(a));
}
__device__ __forceinline__ void mma16816(float* c, const uint32_t* a, const uint32_t* b) {
    asm volatile("mma.sync.aligned.m16n8k16.row.col.f32.bf16.bf16.f32 "
                 "{%0,%1,%2,%3},{%4,%5,%6,%7},{%8,%9},{%0,%1,%2,%3};"
                 : "+f"(c[0]), "+f"(c[1]), "+f"(c[2]), "+f"(c[3])
                 : "r"(a[0]), "r"(a[1]), "r"(a[2]), "r"(a[3]), "r"(b[0]), "r"(b[1]));
}
#define CPA16(dst, src) \
    asm volatile("cp.async.cg.shared.global [%0], [%1], 16;" :: "r"(dst), "l"(src))
#define CP_COMMIT() asm volatile("cp.async.commit_group;")
#define CP_WAIT0()  asm volatile("cp.async.wait_group 0;")

__device__ __forceinline__ uint32_t pack_bf2(__nv_bfloat16 a, __nv_bfloat16 b) {
    __nv_bfloat162 t(a, b);
    return *(uint32_t*)&t;
}
__device__ __forceinline__ void split2(float v, __nv_bfloat16& h, __nv_bfloat16& l) {
    h = __float2bfloat16(v);
    l = __float2bfloat16(v - __bfloat162float(h));
}

// exp(s/16) via FMA-only exp2 (avoids the MUFU rt-8 wall). err ~1.2e-7
__device__ __forceinline__ float fexp16(float s) {
    const float LOG2E16 = 0.09016844005556021f;  // log2(e)/16
    float x = s * LOG2E16;
    float t = x + 12582912.0f;                    // round-to-nearest int
    float n = t - 12582912.0f;
    float f = x - n;
    int ni = __float_as_int(t) - 0x4B400000;
    float p = 1.5403530e-4f;
    p = fmaf(p, f, 1.3333558e-3f);
    p = fmaf(p, f, 9.6181291e-3f);
    p = fmaf(p, f, 5.5504109e-2f);
    p = fmaf(p, f, 2.4022651e-1f);
    p = fmaf(p, f, 6.9314718e-1f);
    p = fmaf(p, f, 1.0f);
    return __int_as_float(__float_as_int(p) + (ni << 23));
}

// ---------------- preprocessing: split X into hi/lo, row-major + transposed ----------------
__global__ void __launch_bounds__(256) split_x_kernel(const float* __restrict__ inp) {
    __shared__ float t[32][33];
    const int b = blockIdx.z;
    const int m0 = blockIdx.x * 32, k0 = blockIdx.y * 32;
    const int tx = threadIdx.x, ty = threadIdx.y;  // 32 x 8
    const float* src = inp + ((size_t)b * NN + m0) * DD + k0;
#pragma unroll
    for (int s = 0; s < 4; s++) {
        const int m = ty + 8 * s;
        const float v = src[(size_t)m * DD + tx];
        t[m][tx] = v;
        __nv_bfloat16 h, l;
        split2(v, h, l);
        const size_t o = ((size_t)b * NN + m0 + m) * DD + k0 + tx;
        g_xhi[o] = h;
        g_xlo[o] = l;
    }
    __syncthreads();
#pragma unroll
    for (int s = 0; s < 4; s++) {
        const int c = ty + 8 * s;
        const float v = t[tx][c];  // X[m0+tx][k0+c]
        __nv_bfloat16 h, l;
        split2(v, h, l);
        const size_t o = ((size_t)b * DD + k0 + c) * NN + m0 + tx;
        g_xthi[o] = h;
        g_xtlo[o] = l;
    }
}

__global__ void __launch_bounds__(256) split_wt_kernel(const float* __restrict__ W) {
    __shared__ float t[32][33];
    const int k0 = blockIdx.x * 32, n0 = blockIdx.y * 32;
    const int tx = threadIdx.x, ty = threadIdx.y;
#pragma unroll
    for (int s = 0; s < 4; s++) t[ty + 8 * s][tx] = W[(size_t)(k0 + ty + 8 * s) * DD + n0 + tx];
    __syncthreads();
#pragma unroll
    for (int s = 0; s < 4; s++) {
        const int k = ty + 8 * s;
        const float v = t[k][tx];  // W[k0+k][n0+tx]
        __nv_bfloat16 h, l;
        split2(v, h, l);
        const size_t o = (size_t)(n0 + tx) * DD + k0 + k;
        g_wthi[o] = h;
        g_wtlo[o] = l;
    }
}

// Wait: split_wt writes g_wt[n][k] = W[k][n]; need transposed indexing in write:
// (handled above: o indexed by [n][k], value W[k][n]) -- but writes are strided.
// Fix via shared-mem transpose read pattern: t[k][tx=n]; read t[ty...][tx]? kept simple:
// writes stride DD along tx? o = (n0+tx)*DD + ... -> stride 256 floats between lanes: ok (2B each, small matrix).

// ---------------- fused attention: Y = (exp(XX^T/16)*adj / rowsum) @ X ----------------
// smem offsets (bytes)
#define S_QHI 0u
#define S_QLO 33792u
#define S_KHI 67584u
#define S_KLO 101376u
#define S_VHI 135168u
#define S_VLO 172032u
#define S_PHI 208896u
#define S_PLO 218112u
#define S_DEN 227328u
#define SMEM_ATTN 227840u

__global__ void __launch_bounds__(256, 1) attn_kernel(const float* __restrict__ adj) {
    extern __shared__ char smem[];
    const uint32_t sb = smem_u32(smem);
    const int tid = threadIdx.x;
    const int wid = tid >> 5, lane = tid & 31;
    const int s = wid >> 1, hs = wid & 1;
    const int lane7 = lane & 7, l34 = (lane >> 3) & 1, l4 = lane >> 4;

    const int bb = blockIdx.x >> 5;
    const int i0 = (blockIdx.x & 31) * 64;

    const __nv_bfloat16* __restrict__ xhiB = g_xhi + (size_t)bb * NN * DD;
    const __nv_bfloat16* __restrict__ xloB = g_xlo + (size_t)bb * NN * DD;
    const __nv_bfloat16* __restrict__ xthiB = g_xthi + (size_t)bb * DD * NN;
    const __nv_bfloat16* __restrict__ xtloB = g_xtlo + (size_t)bb * DD * NN;
    const float* __restrict__ adjB = adj + (size_t)bb * NN * NN;

    // ---- Q tiles (rows i0..i0+63) via cp.async, once ----
#pragma unroll
    for (int it = 0; it < 8; it++) {
        const int idx = it * 256 + tid;
        const int row = idx >> 5, c16 = idx & 31;
        CPA16(sb + S_QHI + row * 528 + c16 * 16, xhiB + (size_t)(i0 + row) * DD + c16 * 8);
        CPA16(sb + S_QLO + row * 528 + c16 * 16, xloB + (size_t)(i0 + row) * DD + c16 * 8);
    }
    CP_COMMIT();

    // fragment address precompute
    const int aRow = s * 16 + lane7 + l34 * 8;     // A-frag row (S and PV share pattern)
    const uint32_t aQhi = sb + S_QHI + aRow * 528 + (l4 * 8) * 2;
    const uint32_t aQlo = sb + S_QLO + aRow * 528 + (l4 * 8) * 2;
    const int bRowS = hs * 32 + l4 * 8 + lane7;    // B-frag K-row for S
    const uint32_t bKhi = sb + S_KHI + bRowS * 528 + (l34 * 8) * 2;
    const uint32_t bKlo = sb + S_KLO + bRowS * 528 + (l34 * 8) * 2;
    const uint32_t aPhi = sb + S_PHI + aRow * 144 + (l4 * 8) * 2;
    const uint32_t aPlo = sb + S_PLO + aRow * 144 + (l4 * 8) * 2;
    const int vRow = hs * 128 + l4 * 8 + lane7;    // B-frag V^T row (= out col) for PV
    const uint32_t bVhi = sb + S_VHI + vRow * 144 + (l34 * 8) * 2;
    const uint32_t bVlo = sb + S_VLO + vRow * 144 + (l34 * 8) * 2;

    const int r0 = s * 16 + (lane >> 2);
    const int cb = hs * 32 + (lane & 3) * 2;
    const uint32_t psHi0 = sb + S_PHI + r0 * 144 + cb * 2;
    const uint32_t psLo0 = sb + S_PLO + r0 * 144 + cb * 2;

    float oacc[16][4];
#pragma unroll
    for (int i = 0; i < 16; i++)
#pragma unroll
        for (int j = 0; j < 4; j++) oacc[i][j] = 0.f;
    float den0 = 0.f, den1 = 0.f;

    for (int ch = 0; ch < NCHUNK; ch++) {
        const int m0 = ch * TM;
        __syncthreads();  // previous PV / S consumers done

        // ---- load K (hi/lo) and V^T (hi/lo) tiles ----
#pragma unroll
        for (int it = 0; it < 8; it++) {
            const int idx = it * 256 + tid;
            const int row = idx >> 5, c16 = idx & 31;
            CPA16(sb + S_KHI + row * 528 + c16 * 16, xhiB + (size_t)(m0 + row) * DD + c16 * 8);
            CPA16(sb + S_KLO + row * 528 + c16 * 16, xloB + (size_t)(m0 + row) * DD + c16 * 8);
        }
#pragma unroll
        for (int it = 0; it < 8; it++) {
            const int idx = it * 256 + tid;
            const int row = idx >> 3, c16 = idx & 7;
            CPA16(sb + S_VHI + row * 144 + c16 * 16, xthiB + (size_t)row * NN + m0 + c16 * 8);
            CPA16(sb + S_VLO + row * 144 + c16 * 16, xtloB + (size_t)row * NN + m0 + c16 * 8);
        }
        CP_COMMIT();
        CP_WAIT0();
        __syncthreads();

        // ---- S = Qh*Kh + Qh*Kl + Ql*Kh  (warp: 16 rows x 32 cols) ----
        float sacc[4][4];
#pragma unroll
        for (int i = 0; i < 4; i++)
#pragma unroll
            for (int j = 0; j < 4; j++) sacc[i][j] = 0.f;

#pragma unroll 4
        for (int kk = 0; kk < 16; kk++) {
            const uint32_t ko = kk * 32;  // 16 elems * 2B
            uint32_t ah[4], al[4], bh0[4], bh1[4], bl0[4], bl1[4];
            ldsm4(ah, aQhi + ko);
            ldsm4(al, aQlo + ko);
            ldsm4(bh0, bKhi + ko);
            ldsm4(bh1, bKhi + 16 * 528 + ko);
            ldsm4(bl0, bKlo + ko);
            ldsm4(bl1, bKlo + 16 * 528 + ko);
            mma16816(sacc[0], ah, bh0 + 0);
            mma16816(sacc[1], ah, bh0 + 2);
            mma16816(sacc[2], ah, bh1 + 0);
            mma16816(sacc[3], ah, bh1 + 2);
            mma16816(sacc[0], ah, bl0 + 0);
            mma16816(sacc[1], ah, bl0 + 2);
            mma16816(sacc[2], ah, bl1 + 0);
            mma16816(sacc[3], ah, bl1 + 2);
            mma16816(sacc[0], al, bh0 + 0);
            mma16816(sacc[1], al, bh0 + 2);
            mma16816(sacc[2], al, bh1 + 0);
            mma16816(sacc[3], al, bh1 + 2);
        }

        // ---- epilogue: P = exp(S/16)*adj; denom; split P -> smem bf16 hi/lo ----
        const float* adjR0 = adjB + (size_t)(i0 + r0) * NN + m0 + cb;
        const float* adjR1 = adjR0 + 8 * NN;
#pragma unroll
        for (int nt = 0; nt < 4; nt++) {
            const float2 a0 = *(const float2*)(adjR0 + nt * 8);
            const float2 a1 = *(const float2*)(adjR1 + nt * 8);
            const float p00 = fexp16(sacc[nt][0]) * a0.x;
            const float p01 = fexp16(sacc[nt][1]) * a0.y;
            const float p10 = fexp16(sacc[nt][2]) * a1.x;
            const float p11 = fexp16(sacc[nt][3]) * a1.y;
            den0 += p00 + p01;
            den1 += p10 + p11;
            __nv_bfloat16 h00, l00, h01, l01, h10, l10, h11, l11;
            split2(p00, h00, l00);
            split2(p01, h01, l01);
            split2(p10, h10, l10);
            split2(p11, h11, l11);
            *(uint32_t*)(smem + (psHi0 - sb) + nt * 16) = pack_bf2(h00, h01);
            *(uint32_t*)(smem + (psHi0 - sb) + 8 * 144 + nt * 16) = pack_bf2(h10, h11);
            *(uint32_t*)(smem + (psLo0 - sb) + nt * 16) = pack_bf2(l00, l01);
            *(uint32_t*)(smem + (psLo0 - sb) + 8 * 144 + nt * 16) = pack_bf2(l10, l11);
        }
        __syncthreads();

        // ---- O += Ph*Vh + Ph*Vl + Pl*Vh  (warp: 16 rows x 128 cols) ----
#pragma unroll
        for (int kk = 0; kk < 4; kk++) {
            const uint32_t ko = kk * 32;
            uint32_t aph[4], apl[4];
            ldsm4(aph, aPhi + ko);
            ldsm4(apl, aPlo + ko);
#pragma unroll
            for (int nt2 = 0; nt2 < 8; nt2++) {
                uint32_t bvh[4], bvl[4];
                ldsm4(bvh, bVhi + nt2 * (16 * 144) + ko);
                ldsm4(bvl, bVlo + nt2 * (16 * 144) + ko);
                mma16816(oacc[nt2 * 2], aph, bvh + 0);
                mma16816(oacc[nt2 * 2 + 1], aph, bvh + 2);
                mma16816(oacc[nt2 * 2], aph, bvl + 0);
                mma16816(oacc[nt2 * 2 + 1], aph, bvl + 2);
                mma16816(oacc[nt2 * 2], apl, bvh + 0);
                mma16816(oacc[nt2 * 2 + 1], apl, bvh + 2);
            }
        }
    }

    // ---- denom cross-warp combine + write Y ----
    den0 += __shfl_xor_sync(0xFFFFFFFFu, den0, 1);
    den0 += __shfl_xor_sync(0xFFFFFFFFu, den0, 2);
    den1 += __shfl_xor_sync(0xFFFFFFFFu, den1, 1);
    den1 += __shfl_xor_sync(0xFFFFFFFFu, den1, 2);
    float* den_sm = (float*)(smem + S_DEN);  // [2][64]
    __syncthreads();
    if ((lane & 3) == 0) {
        den_sm[hs * 64 + r0] = den0;
        den_sm[hs * 64 + r0 + 8] = den1;
    }
    __syncthreads();
    const float invd0 = 1.0f / (den_sm[r0] + den_sm[64 + r0] + 1e-10f);
    const float invd1 = 1.0f / (den_sm[r0 + 8] + den_sm[64 + r0 + 8] + 1e-10f);

    float* yR0 = g_y + ((size_t)bb * NN + i0 + r0) * DD + hs * 128 + (lane & 3) * 2;
    float* yR1 = yR0 + 8 * DD;
#pragma unroll
    for (int nt = 0; nt < 16; nt++) {
        *(float2*)(yR0 + nt * 8) = make_float2(oacc[nt][0] * invd0, oacc[nt][1] * invd0);
        *(float2*)(yR1 + nt * 8) = make_float2(oacc[nt][2] * invd1, oacc[nt][3] * invd1);
    }
}

// ---------------- final: out = leaky_relu(Y @ W + b) ----------------
#define YW_YHI 0u
#define YW_YLO 33792u
#define YW_WHI 67584u
#define YW_WLO 104448u
#define SMEM_YW 141312u

__global__ void __launch_bounds__(256, 1) ywb_kernel(const float* __restrict__ bvec,
                                                     float* __restrict__ out) {
    extern __shared__ char smem[];
    const uint32_t sb = smem_u32(smem);
    const int tid = threadIdx.x;
    const int wid = tid >> 5, lane = tid & 31;
    const int s = wid >> 1, hs = wid & 1;
    const int lane7 = lane & 7, l34 = (lane >> 3) & 1, l4 = lane >> 4;
    const int R0 = blockIdx.x * 64;

    // load + split Y rows R0..R0+63 into smem bf16 hi/lo
#pragma unroll
    for (int it = 0; it < 16; it++) {
        const int idx = it * 256 + tid;
        const int row = idx >> 6, c4 = idx & 63;
        const float4 v = *(const float4*)(g_y + (size_t)(R0 + row) * DD + c4 * 4);
        __nv_bfloat16 h0, l0, h1, l1, h2, l2, h3, l3;
        split2(v.x, h0, l0);
        split2(v.y, h1, l1);
        split2(v.z, h2, l2);
        split2(v.w, h3, l3);
        uint2 hw = make_uint2(pack_bf2(h0, h1), pack_bf2(h2, h3));
        uint2 lw = make_uint2(pack_bf2(l0, l1), pack_bf2(l2, l3));
        *(uint2*)(smem + YW_YHI + row * 528 + c4 * 8) = hw;
        *(uint2*)(smem + YW_YLO + row * 528 + c4 * 8) = lw;
    }

    const int aRow = s * 16 + lane7 + l34 * 8;
    const uint32_t aYhi = sb + YW_YHI + aRow * 528 + (l4 * 8) * 2;
    const uint32_t aYlo = sb + YW_YLO + aRow * 528 + (l4 * 8) * 2;
    const int wRow = hs * 128 + l4 * 8 + lane7;
    const uint32_t bWhi = sb + YW_WHI + wRow * 144 + (l34 * 8) * 2;
    const uint32_t bWlo = sb + YW_WLO + wRow * 144 + (l34 * 8) * 2;

    float oacc[16][4];
#pragma unroll
    for (int i = 0; i < 16; i++)
#pragma unroll
        for (int j = 0; j < 4; j++) oacc[i][j] = 0.f;

    for (int kc = 0; kc < 4; kc++) {
        __syncthreads();
        // load W^T k-chunk (256 n-rows x 64 k) hi/lo
#pragma unroll
        for (int it = 0; it < 8; it++) {
            const int idx = it * 256 + tid;
            const int row = idx >> 3, c16 = idx & 7;
            CPA16(sb + YW_WHI + row * 144 + c16 * 16, g_wthi + (size_t)row * DD + kc * 64 + c16 * 8);
            CPA16(sb + YW_WLO + row * 144 + c16 * 16, g_wtlo + (size_t)row * DD + kc * 64 + c16 * 8);
        }
        CP_COMMIT();
        CP_WAIT0();
        __syncthreads();

#pragma unroll
        for (int kk = 0; kk < 4; kk++) {
            const uint32_t koA = (kc * 64 + kk * 16) * 2;
            const uint32_t koB = kk * 32;
            uint32_t ah[4], al[4];
            ldsm4(ah, aYhi + koA);
            ldsm4(al, aYlo + koA);
#pragma unroll
            for (int nt2 = 0; nt2 < 8; nt2++) {
                uint32_t bh[4], bl[4];
                ldsm4(bh, bWhi + nt2 * (16 * 144) + koB);
                ldsm4(bl, bWlo + nt2 * (16 * 144) + koB);
                mma16816(oacc[nt2 * 2], ah, bh + 0);
                mma16816(oacc[nt2 * 2 + 1], ah, bh + 2);
                mma16816(oacc[nt2 * 2], ah, bl + 0);
                mma16816(oacc[nt2 * 2 + 1], ah, bl + 2);
                mma16816(oacc[nt2 * 2], al, bh + 0);
                mma16816(oacc[nt2 * 2 + 1], al, bh + 2);
            }
        }
    }

    // epilogue: bias + leaky relu
    const int r0 = s * 16 + (lane >> 2);
    const int c0 = hs * 128 + (lane & 3) * 2;
    float* oR0 = out + (size_t)(R0 + r0) * DD + c0;
    float* oR1 = oR0 + 8 * DD;
#pragma unroll
    for (int nt = 0; nt < 16; nt++) {
        const float2 bv = *(const float2*)(bvec + c0 + nt * 8);
        float v0 = oacc[nt][0] + bv.x, v1 = oacc[nt][1] + bv.y;
        float v2 = oacc[nt][2] + bv.x, v3 = oacc[nt][3] + bv.y;
        v0 = v0 > 0.f ? v0 : 0.01f * v0;
        v1 = v1 > 0.f ? v1 : 0.01f * v1;
        v2 = v2 > 0.f ? v2 : 0.01f * v2;
        v3 = v3 > 0.f ? v3 : 0.01f * v3;
        *(float2*)(oR0 + nt * 8) = make_float2(v0, v1);
        *(float2*)(oR1 + nt * 8) = make_float2(v2, v3);
    }
}

// ---------------------------------------------------------------------------
extern "C" void kernel_launch(void* const* d_in, const int* in_sizes, int n_in,
                              void* d_out, int out_size) {
    const float* inp = (const float*)d_in[0];
    const float* adj = (const float*)d_in[1];
    const float* W = (const float*)d_in[2];
    const float* b = (const float*)d_in[3];
    float* out = (float*)d_out;

    split_x_kernel<<<dim3(NN / 32, DD / 32, BB), dim3(32, 8)>>>(inp);
    split_wt_kernel<<<dim3(DD / 32, DD / 32), dim3(32, 8)>>>(W);

    cudaFuncSetAttribute(attn_kernel, cudaFuncAttributeMaxDynamicSharedMemorySize, SMEM_ATTN);
    attn_kernel<<<BB * (NN / 64), 256, SMEM_ATTN>>>(adj);

    cudaFuncSetAttribute(ywb_kernel, cudaFuncAttributeMaxDynamicSharedMemorySize, SMEM_YW);
    ywb_kernel<<<BN / 64, 256, SMEM_YW>>>(b, out);
}

// round 4
// speedup vs baseline: 4.8584x; 1.1374x over previous
#include <cuda_runtime.h>
#include <cuda_bf16.h>
#include <stdint.h>

#define BB 8
#define NN 2048
#define DD 256
#define BN (BB * NN)
#define TM 64
#define NCHUNK (NN / TM)

// ---------------- device scratch (allocation-free) ----------------
__device__ __nv_bfloat16 g_xhi[BN * DD];        // X row-major hi
__device__ __nv_bfloat16 g_xlo[BN * DD];        // X row-major lo
__device__ __nv_bfloat16 g_xthi[BB * DD * NN];  // X^T [b][k][m] hi
__device__ __nv_bfloat16 g_xtlo[BB * DD * NN];  // X^T [b][k][m] lo
__device__ __nv_bfloat16 g_wthi[DD * DD];       // W^T [n][k] hi
__device__ __nv_bfloat16 g_wtlo[DD * DD];       // W^T [n][k] lo
__device__ float g_y[BN * DD];                  // Y = attn @ X (normalized)

// ---------------- helpers ----------------
__device__ __forceinline__ uint32_t smem_u32(const void* p) {
    uint32_t a;
    asm("{ .reg .u64 t; cvta.to.shared.u64 t, %1; cvt.u32.u64 %0, t; }" : "=r"(a) : "l"(p));
    return a;
}
__device__ __forceinline__ void ldsm4(uint32_t* r, uint32_t a) {
    asm volatile("ldmatrix.sync.aligned.m8n8.x4.shared.b16 {%0,%1,%2,%3}, [%4];"
                 : "=r"(r[0]), "=r"(r[1]), "=r"(r[2]), "=r"(r[3]) : "r"(a));
}
__device__ __forceinline__ void mma16816(float* c, const uint32_t* a, const uint32_t* b) {
    asm volatile("mma.sync.aligned.m16n8k16.row.col.f32.bf16.bf16.f32 "
                 "{%0,%1,%2,%3},{%4,%5,%6,%7},{%8,%9},{%0,%1,%2,%3};"
                 : "+f"(c[0]), "+f"(c[1]), "+f"(c[2]), "+f"(c[3])
                 : "r"(a[0]), "r"(a[1]), "r"(a[2]), "r"(a[3]), "r"(b[0]), "r"(b[1]));
}
#define CPA16(dst, src) \
    asm volatile("cp.async.cg.shared.global [%0], [%1], 16;" :: "r"(dst), "l"(src))
#define CP_COMMIT() asm volatile("cp.async.commit_group;")
#define CP_WAIT(n)  asm volatile("cp.async.wait_group %0;" :: "n"(n))

__device__ __forceinline__ uint32_t pack_bf2(__nv_bfloat16 a, __nv_bfloat16 b) {
    __nv_bfloat162 t(a, b);
    return *(uint32_t*)&t;
}
__device__ __forceinline__ void split2(float v, __nv_bfloat16& h, __nv_bfloat16& l) {
    h = __float2bfloat16(v);
    l = __float2bfloat16(v - __bfloat162float(h));
}

// exp(s/16) via FMA-only exp2 (avoids MUFU rt-8 wall). err ~1.2e-7
__device__ __forceinline__ float fexp16(float s) {
    const float LOG2E16 = 0.09016844005556021f;  // log2(e)/16
    float x = s * LOG2E16;
    float t = x + 12582912.0f;
    float n = t - 12582912.0f;
    float f = x - n;
    int ni = __float_as_int(t) - 0x4B400000;
    float p = 1.5403530e-4f;
    p = fmaf(p, f, 1.3333558e-3f);
    p = fmaf(p, f, 9.6181291e-3f);
    p = fmaf(p, f, 5.5504109e-2f);
    p = fmaf(p, f, 2.4022651e-1f);
    p = fmaf(p, f, 6.9314718e-1f);
    p = fmaf(p, f, 1.0f);
    return __int_as_float(__float_as_int(p) + (ni << 23));
}

// ---------------- preprocessing ----------------
__global__ void __launch_bounds__(256) split_x_kernel(const float* __restrict__ inp) {
    __shared__ float t[32][33];
    const int b = blockIdx.z;
    const int m0 = blockIdx.x * 32, k0 = blockIdx.y * 32;
    const int tx = threadIdx.x, ty = threadIdx.y;
    const float* src = inp + ((size_t)b * NN + m0) * DD + k0;
#pragma unroll
    for (int s = 0; s < 4; s++) {
        const int m = ty + 8 * s;
        const float v = src[(size_t)m * DD + tx];
        t[m][tx] = v;
        __nv_bfloat16 h, l;
        split2(v, h, l);
        const size_t o = ((size_t)b * NN + m0 + m) * DD + k0 + tx;
        g_xhi[o] = h;
        g_xlo[o] = l;
    }
    __syncthreads();
#pragma unroll
    for (int s = 0; s < 4; s++) {
        const int c = ty + 8 * s;
        const float v = t[tx][c];
        __nv_bfloat16 h, l;
        split2(v, h, l);
        const size_t o = ((size_t)b * DD + k0 + c) * NN + m0 + tx;
        g_xthi[o] = h;
        g_xtlo[o] = l;
    }
}

__global__ void __launch_bounds__(256) split_wt_kernel(const float* __restrict__ W) {
    __shared__ float t[32][33];
    const int k0 = blockIdx.x * 32, n0 = blockIdx.y * 32;
    const int tx = threadIdx.x, ty = threadIdx.y;
#pragma unroll
    for (int s = 0; s < 4; s++) t[ty + 8 * s][tx] = W[(size_t)(k0 + ty + 8 * s) * DD + n0 + tx];
    __syncthreads();
#pragma unroll
    for (int s = 0; s < 4; s++) {
        const int k = ty + 8 * s;
        const float v = t[k][tx];
        __nv_bfloat16 h, l;
        split2(v, h, l);
        const size_t o = (size_t)(n0 + tx) * DD + k0 + k;
        g_wthi[o] = h;
        g_wtlo[o] = l;
    }
}

// ---------------- fused attention: Y = (exp(XX^T/16)*adj / rowsum) @ X ----------------
#define S_QHI 0u
#define S_QLO 33792u
#define S_KHI 67584u
#define S_KLO 101376u
#define S_VHI 135168u
#define S_VLO 172032u
#define S_PHI 208896u
#define S_PLO 218112u
#define S_DEN 227328u
#define SMEM_ATTN 227840u

__global__ void __launch_bounds__(256, 1) attn_kernel(const float* __restrict__ adj) {
    extern __shared__ char smem[];
    const uint32_t sb = smem_u32(smem);
    const int tid = threadIdx.x;
    const int wid = tid >> 5, lane = tid & 31;
    const int s = wid >> 1, hs = wid & 1;
    const int lane7 = lane & 7, l34 = (lane >> 3) & 1, l4 = lane >> 4;

    const int bb = blockIdx.x >> 5;
    const int i0 = (blockIdx.x & 31) * 64;

    const __nv_bfloat16* __restrict__ xhiB = g_xhi + (size_t)bb * NN * DD;
    const __nv_bfloat16* __restrict__ xloB = g_xlo + (size_t)bb * NN * DD;
    const __nv_bfloat16* __restrict__ xthiB = g_xthi + (size_t)bb * DD * NN;
    const __nv_bfloat16* __restrict__ xtloB = g_xtlo + (size_t)bb * DD * NN;
    const float* __restrict__ adjB = adj + (size_t)bb * NN * NN;

    const int ldRowK = tid >> 5, ldC16K = tid & 31;   // K/Q loaders
    const int ldRowV = tid >> 3, ldC16V = tid & 7;    // V loaders

    // ---- group G0: Q + K(0) + V(0) ----
#pragma unroll
    for (int it = 0; it < 8; it++) {
        const int row = ldRowK + it * 8;
        CPA16(sb + S_QHI + row * 528 + ldC16K * 16, xhiB + (size_t)(i0 + row) * DD + ldC16K * 8);
        CPA16(sb + S_QLO + row * 528 + ldC16K * 16, xloB + (size_t)(i0 + row) * DD + ldC16K * 8);
        CPA16(sb + S_KHI + row * 528 + ldC16K * 16, xhiB + (size_t)row * DD + ldC16K * 8);
        CPA16(sb + S_KLO + row * 528 + ldC16K * 16, xloB + (size_t)row * DD + ldC16K * 8);
    }
#pragma unroll
    for (int it = 0; it < 8; it++) {
        const int row = ldRowV + it * 32;
        CPA16(sb + S_VHI + row * 144 + ldC16V * 16, xthiB + (size_t)row * NN + ldC16V * 8);
        CPA16(sb + S_VLO + row * 144 + ldC16V * 16, xtloB + (size_t)row * NN + ldC16V * 8);
    }
    CP_COMMIT();

    // fragment addresses
    const int aRow = s * 16 + lane7 + l34 * 8;
    const uint32_t aQhi = sb + S_QHI + aRow * 528 + (l4 * 8) * 2;
    const uint32_t aQlo = sb + S_QLO + aRow * 528 + (l4 * 8) * 2;
    const int bRowS = hs * 32 + l4 * 8 + lane7;
    const uint32_t bKhi = sb + S_KHI + bRowS * 528 + (l34 * 8) * 2;
    const uint32_t bKlo = sb + S_KLO + bRowS * 528 + (l34 * 8) * 2;
    const uint32_t aPhi = sb + S_PHI + aRow * 144 + (l4 * 8) * 2;
    const uint32_t aPlo = sb + S_PLO + aRow * 144 + (l4 * 8) * 2;
    const int vRow = hs * 128 + l4 * 8 + lane7;
    const uint32_t bVhi = sb + S_VHI + vRow * 144 + (l34 * 8) * 2;
    const uint32_t bVlo = sb + S_VLO + vRow * 144 + (l34 * 8) * 2;

    const int r0 = s * 16 + (lane >> 2);
    const int cb = hs * 32 + (lane & 3) * 2;
    const uint32_t psHi0 = sb + S_PHI + r0 * 144 + cb * 2;
    const uint32_t psLo0 = sb + S_PLO + r0 * 144 + cb * 2;

    float oacc[16][4];
#pragma unroll
    for (int i = 0; i < 16; i++)
#pragma unroll
        for (int j = 0; j < 4; j++) oacc[i][j] = 0.f;
    float den0 = 0.f, den1 = 0.f;

    for (int ch = 0; ch < NCHUNK; ch++) {
        const int m0 = ch * TM;
        if (ch == 0) CP_WAIT(0);   // Q,K0,V0
        else         CP_WAIT(1);   // K(ch) done; V(ch) may still be in flight
        __syncthreads();

        // prefetch adj tile into registers (latency hides under S MMAs)
        const float* adjR0 = adjB + (size_t)(i0 + r0) * NN + m0 + cb;
        const float* adjR1 = adjR0 + 8 * NN;
        float2 aj0[4], aj1[4];
#pragma unroll
        for (int nt = 0; nt < 4; nt++) {
            aj0[nt] = __ldg((const float2*)(adjR0 + nt * 8));
            aj1[nt] = __ldg((const float2*)(adjR1 + nt * 8));
        }

        // ---- S = Qh*Kh + Qh*Kl + Ql*Kh ----
        float sacc[4][4];
#pragma unroll
        for (int i = 0; i < 4; i++)
#pragma unroll
            for (int j = 0; j < 4; j++) sacc[i][j] = 0.f;

#pragma unroll 4
        for (int kk = 0; kk < 16; kk++) {
            const uint32_t ko = kk * 32;
            uint32_t ah[4], al[4], bh0[4], bh1[4], bl0[4], bl1[4];
            ldsm4(ah, aQhi + ko);
            ldsm4(al, aQlo + ko);
            ldsm4(bh0, bKhi + ko);
            ldsm4(bh1, bKhi + 16 * 528 + ko);
            ldsm4(bl0, bKlo + ko);
            ldsm4(bl1, bKlo + 16 * 528 + ko);
            mma16816(sacc[0], ah, bh0 + 0);
            mma16816(sacc[1], ah, bh0 + 2);
            mma16816(sacc[2], ah, bh1 + 0);
            mma16816(sacc[3], ah, bh1 + 2);
            mma16816(sacc[0], ah, bl0 + 0);
            mma16816(sacc[1], ah, bl0 + 2);
            mma16816(sacc[2], ah, bl1 + 0);
            mma16816(sacc[3], ah, bl1 + 2);
            mma16816(sacc[0], al, bh0 + 0);
            mma16816(sacc[1], al, bh0 + 2);
            mma16816(sacc[2], al, bh1 + 0);
            mma16816(sacc[3], al, bh1 + 2);
        }

        // ---- epilogue: P = exp(S/16)*adj; denom; split -> smem ----
#pragma unroll
        for (int nt = 0; nt < 4; nt++) {
            const float p00 = fexp16(sacc[nt][0]) * aj0[nt].x;
            const float p01 = fexp16(sacc[nt][1]) * aj0[nt].y;
            const float p10 = fexp16(sacc[nt][2]) * aj1[nt].x;
            const float p11 = fexp16(sacc[nt][3]) * aj1[nt].y;
            den0 += p00 + p01;
            den1 += p10 + p11;
            __nv_bfloat16 h00, l00, h01, l01, h10, l10, h11, l11;
            split2(p00, h00, l00);
            split2(p01, h01, l01);
            split2(p10, h10, l10);
            split2(p11, h11, l11);
            *(uint32_t*)(smem + (psHi0 - sb) + nt * 16) = pack_bf2(h00, h01);
            *(uint32_t*)(smem + (psHi0 - sb) + 8 * 144 + nt * 16) = pack_bf2(h10, h11);
            *(uint32_t*)(smem + (psLo0 - sb) + nt * 16) = pack_bf2(l00, l01);
            *(uint32_t*)(smem + (psLo0 - sb) + 8 * 144 + nt * 16) = pack_bf2(l10, l11);
        }
        __syncthreads();  // P visible; K(ch) fully consumed by all warps

        // ---- issue K(ch+1) loads (overlap PV) ----
        {
            const int mn = ((ch + 1) & (NCHUNK - 1)) * TM;
#pragma unroll
            for (int it = 0; it < 8; it++) {
                const int row = ldRowK + it * 8;
                CPA16(sb + S_KHI + row * 528 + ldC16K * 16, xhiB + (size_t)(mn + row) * DD + ldC16K * 8);
                CPA16(sb + S_KLO + row * 528 + ldC16K * 16, xloB + (size_t)(mn + row) * DD + ldC16K * 8);
            }
            CP_COMMIT();
        }
        CP_WAIT(1);  // V(ch) done; K(ch+1) pending

        // ---- O += Ph*Vh + Ph*Vl + Pl*Vh ----
#pragma unroll
        for (int kk = 0; kk < 4; kk++) {
            const uint32_t ko = kk * 32;
            uint32_t aph[4], apl[4];
            ldsm4(aph, aPhi + ko);
            ldsm4(apl, aPlo + ko);
#pragma unroll
            for (int nt2 = 0; nt2 < 8; nt2++) {
                uint32_t bvh[4], bvl[4];
                ldsm4(bvh, bVhi + nt2 * (16 * 144) + ko);
                ldsm4(bvl, bVlo + nt2 * (16 * 144) + ko);
                mma16816(oacc[nt2 * 2], aph, bvh + 0);
                mma16816(oacc[nt2 * 2 + 1], aph, bvh + 2);
                mma16816(oacc[nt2 * 2], aph, bvl + 0);
                mma16816(oacc[nt2 * 2 + 1], aph, bvl + 2);
                mma16816(oacc[nt2 * 2], apl, bvh + 0);
                mma16816(oacc[nt2 * 2 + 1], apl, bvh + 2);
            }
        }
        __syncthreads();  // V(ch) fully consumed by all warps

        // ---- issue V(ch+1) loads (overlap next S) ----
        {
            const int mn = ((ch + 1) & (NCHUNK - 1)) * TM;
#pragma unroll
            for (int it = 0; it < 8; it++) {
                const int row = ldRowV + it * 32;
                CPA16(sb + S_VHI + row * 144 + ldC16V * 16, xthiB + (size_t)row * NN + mn + ldC16V * 8);
                CPA16(sb + S_VLO + row * 144 + ldC16V * 16, xtloB + (size_t)row * NN + mn + ldC16V * 8);
            }
            CP_COMMIT();
        }
    }

    // ---- denom combine + write Y ----
    den0 += __shfl_xor_sync(0xFFFFFFFFu, den0, 1);
    den0 += __shfl_xor_sync(0xFFFFFFFFu, den0, 2);
    den1 += __shfl_xor_sync(0xFFFFFFFFu, den1, 1);
    den1 += __shfl_xor_sync(0xFFFFFFFFu, den1, 2);
    float* den_sm = (float*)(smem + S_DEN);
    __syncthreads();
    if ((lane & 3) == 0) {
        den_sm[hs * 64 + r0] = den0;
        den_sm[hs * 64 + r0 + 8] = den1;
    }
    __syncthreads();
    const float invd0 = 1.0f / (den_sm[r0] + den_sm[64 + r0] + 1e-10f);
    const float invd1 = 1.0f / (den_sm[r0 + 8] + den_sm[64 + r0 + 8] + 1e-10f);

    float* yR0 = g_y + ((size_t)bb * NN + i0 + r0) * DD + hs * 128 + (lane & 3) * 2;
    float* yR1 = yR0 + 8 * DD;
#pragma unroll
    for (int nt = 0; nt < 16; nt++) {
        *(float2*)(yR0 + nt * 8) = make_float2(oacc[nt][0] * invd0, oacc[nt][1] * invd0);
        *(float2*)(yR1 + nt * 8) = make_float2(oacc[nt][2] * invd1, oacc[nt][3] * invd1);
    }
}

// ---------------- final: out = leaky_relu(Y @ W + b), W double-buffered ----------------
#define YW_YHI 0u
#define YW_YLO 33792u
#define YW_WHI0 67584u
#define YW_WLO0 104448u
#define YW_WHI1 141312u
#define YW_WLO1 178176u
#define SMEM_YW 215040u

__global__ void __launch_bounds__(256, 1) ywb_kernel(const float* __restrict__ bvec,
                                                     float* __restrict__ out) {
    extern __shared__ char smem[];
    const uint32_t sb = smem_u32(smem);
    const int tid = threadIdx.x;
    const int wid = tid >> 5, lane = tid & 31;
    const int s = wid >> 1, hs = wid & 1;
    const int lane7 = lane & 7, l34 = (lane >> 3) & 1, l4 = lane >> 4;
    const int R0 = blockIdx.x * 64;

    const uint32_t wHiOff[2] = {YW_WHI0, YW_WHI1};
    const uint32_t wLoOff[2] = {YW_WLO0, YW_WLO1};
    const int ldRow = tid >> 3, ldC16 = tid & 7;

    // issue W chunk 0 -> buf0
#pragma unroll
    for (int it = 0; it < 8; it++) {
        const int row = ldRow + it * 32;
        CPA16(sb + YW_WHI0 + row * 144 + ldC16 * 16, g_wthi + (size_t)row * DD + ldC16 * 8);
        CPA16(sb + YW_WLO0 + row * 144 + ldC16 * 16, g_wtlo + (size_t)row * DD + ldC16 * 8);
    }
    CP_COMMIT();

    // load + split Y rows
#pragma unroll
    for (int it = 0; it < 16; it++) {
        const int idx = it * 256 + tid;
        const int row = idx >> 6, c4 = idx & 63;
        const float4 v = *(const float4*)(g_y + (size_t)(R0 + row) * DD + c4 * 4);
        __nv_bfloat16 h0, l0, h1, l1, h2, l2, h3, l3;
        split2(v.x, h0, l0);
        split2(v.y, h1, l1);
        split2(v.z, h2, l2);
        split2(v.w, h3, l3);
        *(uint2*)(smem + YW_YHI + row * 528 + c4 * 8) = make_uint2(pack_bf2(h0, h1), pack_bf2(h2, h3));
        *(uint2*)(smem + YW_YLO + row * 528 + c4 * 8) = make_uint2(pack_bf2(l0, l1), pack_bf2(l2, l3));
    }

    const int aRow = s * 16 + lane7 + l34 * 8;
    const uint32_t aYhi = sb + YW_YHI + aRow * 528 + (l4 * 8) * 2;
    const uint32_t aYlo = sb + YW_YLO + aRow * 528 + (l4 * 8) * 2;
    const int wRow = hs * 128 + l4 * 8 + lane7;
    const uint32_t wFragBase = (uint32_t)(wRow * 144 + (l34 * 8) * 2);

    float oacc[16][4];
#pragma unroll
    for (int i = 0; i < 16; i++)
#pragma unroll
        for (int j = 0; j < 4; j++) oacc[i][j] = 0.f;

    for (int kc = 0; kc < 4; kc++) {
        if (kc < 3) {  // issue next W chunk into other buffer
            const uint32_t bh = wHiOff[(kc + 1) & 1], bl = wLoOff[(kc + 1) & 1];
#pragma unroll
            for (int it = 0; it < 8; it++) {
                const int row = ldRow + it * 32;
                CPA16(sb + bh + row * 144 + ldC16 * 16, g_wthi + (size_t)row * DD + (kc + 1) * 64 + ldC16 * 8);
                CPA16(sb + bl + row * 144 + ldC16 * 16, g_wtlo + (size_t)row * DD + (kc + 1) * 64 + ldC16 * 8);
            }
            CP_COMMIT();
            CP_WAIT(1);
        } else {
            CP_WAIT(0);
        }
        __syncthreads();

        const uint32_t bWhi = sb + wHiOff[kc & 1] + wFragBase;
        const uint32_t bWlo = sb + wLoOff[kc & 1] + wFragBase;
#pragma unroll
        for (int kk = 0; kk < 4; kk++) {
            const uint32_t koA = (kc * 64 + kk * 16) * 2;
            const uint32_t koB = kk * 32;
            uint32_t ah[4], al[4];
            ldsm4(ah, aYhi + koA);
            ldsm4(al, aYlo + koA);
#pragma unroll
            for (int nt2 = 0; nt2 < 8; nt2++) {
                uint32_t bh[4], bl[4];
                ldsm4(bh, bWhi + nt2 * (16 * 144) + koB);
                ldsm4(bl, bWlo + nt2 * (16 * 144) + koB);
                mma16816(oacc[nt2 * 2], ah, bh + 0);
                mma16816(oacc[nt2 * 2 + 1], ah, bh + 2);
                mma16816(oacc[nt2 * 2], ah, bl + 0);
                mma16816(oacc[nt2 * 2 + 1], ah, bl + 2);
                mma16816(oacc[nt2 * 2], al, bh + 0);
                mma16816(oacc[nt2 * 2 + 1], al, bh + 2);
            }
        }
        __syncthreads();
    }

    const int r0 = s * 16 + (lane >> 2);
    const int c0 = hs * 128 + (lane & 3) * 2;
    float* oR0 = out + (size_t)(R0 + r0) * DD + c0;
    float* oR1 = oR0 + 8 * DD;
#pragma unroll
    for (int nt = 0; nt < 16; nt++) {
        const float2 bv = *(const float2*)(bvec + c0 + nt * 8);
        float v0 = oacc[nt][0] + bv.x, v1 = oacc[nt][1] + bv.y;
        float v2 = oacc[nt][2] + bv.x, v3 = oacc[nt][3] + bv.y;
        v0 = v0 > 0.f ? v0 : 0.01f * v0;
        v1 = v1 > 0.f ? v1 : 0.01f * v1;
        v2 = v2 > 0.f ? v2 : 0.01f * v2;
        v3 = v3 > 0.f ? v3 : 0.01f * v3;
        *(float2*)(oR0 + nt * 8) = make_float2(v0, v1);
        *(float2*)(oR1 + nt * 8) = make_float2(v2, v3);
    }
}

// ---------------------------------------------------------------------------
extern "C" void kernel_launch(void* const* d_in, const int* in_sizes, int n_in,
                              void* d_out, int out_size) {
    const float* inp = (const float*)d_in[0];
    const float* adj = (const float*)d_in[1];
    const float* W = (const float*)d_in[2];
    const float* b = (const float*)d_in[3];
    float* out = (float*)d_out;

    split_x_kernel<<<dim3(NN / 32, DD / 32, BB), dim3(32, 8)>>>(inp);
    split_wt_kernel<<<dim3(DD / 32, DD / 32), dim3(32, 8)>>>(W);

    cudaFuncSetAttribute(attn_kernel, cudaFuncAttributeMaxDynamicSharedMemorySize, SMEM_ATTN);
    attn_kernel<<<BB * (NN / 64), 256, SMEM_ATTN>>>(adj);

    cudaFuncSetAttribute(ywb_kernel, cudaFuncAttributeMaxDynamicSharedMemorySize, SMEM_YW);
    ywb_kernel<<<BN / 64, 256, SMEM_YW>>>(b, out);
}